// round 5
// baseline (speedup 1.0000x reference)
#include <cuda_runtime.h>
#include <cuda_fp16.h>

// Problem dims (QuantLinearA8W8: M=4096, IN=4096, OUT=11008)
#define MDIM 4096
#define KDIM 4096
#define NDIM 11008

// Scratch (device globals — no allocation allowed in kernel_launch)
__device__ __half g_qx[(size_t)MDIM * KDIM];          // 32 MB: quantized activations (integer values in fp16)
__device__ float  g_rowsum[MDIM];                     // per-row sum of q (for zero-point correction)
__device__ unsigned char g_w8[(size_t)NDIM * KDIM];   // 45 MB: unpacked int4 values 0..15

// ---------------------------------------------------------------------------
// Kernel 1: quantize activations.  q = rint(clip(x,-cv,cv) * 127/cv), exact
// integer stored in fp16.  Also computes rowsum[m] = sum_k q[m,k].
// ---------------------------------------------------------------------------
__global__ void quantize_kernel(const float* __restrict__ x,
                                const float* __restrict__ clampv, int K) {
    const int row = blockIdx.x;
    const int tid = threadIdx.x;
    const float cv  = __ldg(clampv);
    const float inv = 127.0f / cv;
    const float4* xr = reinterpret_cast<const float4*>(x + (size_t)row * K);
    __half2* qr = reinterpret_cast<__half2*>(g_qx + (size_t)row * K);
    float s = 0.0f;
    for (int i = tid; i < K / 4; i += blockDim.x) {
        float4 v = xr[i];
        float q0 = rintf(fminf(fmaxf(v.x, -cv), cv) * inv);
        float q1 = rintf(fminf(fmaxf(v.y, -cv), cv) * inv);
        float q2 = rintf(fminf(fmaxf(v.z, -cv), cv) * inv);
        float q3 = rintf(fminf(fmaxf(v.w, -cv), cv) * inv);
        s += q0 + q1 + q2 + q3;
        qr[2 * i]     = __floats2half2_rn(q0, q1);
        qr[2 * i + 1] = __floats2half2_rn(q2, q3);
    }
    __shared__ float red[256];
    red[tid] = s;
    __syncthreads();
    #pragma unroll
    for (int off = 128; off > 0; off >>= 1) {
        if (tid < off) red[tid] += red[tid + off];
        __syncthreads();
    }
    if (tid == 0) g_rowsum[row] = red[0];
}

// ---------------------------------------------------------------------------
// Kernel 2: unpack packed int4 weights (one byte per int32) into dense int8
// nibble values.  hi nibble -> even k, lo nibble -> odd k.
// ---------------------------------------------------------------------------
__global__ void unpack_kernel(const int* __restrict__ qw, long long ngroups) {
    long long i = (long long)blockIdx.x * blockDim.x + threadIdx.x;
    if (i >= ngroups) return;
    int4 w = __ldg(reinterpret_cast<const int4*>(qw) + i);
    unsigned long long r = 0;
    r |= (unsigned long long)((w.x >> 4) & 15);
    r |= (unsigned long long)(w.x & 15) << 8;
    r |= (unsigned long long)((w.y >> 4) & 15) << 16;
    r |= (unsigned long long)(w.y & 15) << 24;
    r |= (unsigned long long)((w.z >> 4) & 15) << 32;
    r |= (unsigned long long)(w.z & 15) << 40;
    r |= (unsigned long long)((w.w >> 4) & 15) << 48;
    r |= (unsigned long long)(w.w & 15) << 56;
    reinterpret_cast<unsigned long long*>(g_w8)[i] = r;
}

// ---------------------------------------------------------------------------
// Kernel 3: GEMM  C[m,n] = sum_k q[m,k] * v[n,k]   (exact integer via f16 MMA)
// ---------------------------------------------------------------------------
#define BM 128
#define BN 256
#define BK 64
#define PADK 72                          // halves per smem row (+8 pad: conflict-free)
#define STAGE_A (BM * PADK)
#define STAGE_B (BN * PADK)
#define SMEM_BYTES ((2 * STAGE_A + 2 * STAGE_B) * 2)

__device__ __forceinline__ void cp_async16(void* sdst, const void* gsrc) {
    unsigned saddr = (unsigned)__cvta_generic_to_shared(sdst);
    asm volatile("cp.async.cg.shared.global [%0], [%1], 16;\n" :: "r"(saddr), "l"(gsrc));
}
__device__ __forceinline__ void cp_async_commit() { asm volatile("cp.async.commit_group;\n"); }
__device__ __forceinline__ void cp_async_wait0()  { asm volatile("cp.async.wait_group 0;\n"); }

__device__ __forceinline__ void mma16816(float* c, const unsigned* a,
                                         unsigned b0, unsigned b1) {
    asm volatile(
        "mma.sync.aligned.m16n8k16.row.col.f32.f16.f16.f32 "
        "{%0,%1,%2,%3}, {%4,%5,%6,%7}, {%8,%9}, {%0,%1,%2,%3};\n"
        : "+f"(c[0]), "+f"(c[1]), "+f"(c[2]), "+f"(c[3])
        : "r"(a[0]), "r"(a[1]), "r"(a[2]), "r"(a[3]), "r"(b0), "r"(b1));
}

// bytes b (0..15) -> fp16 value b, via (0x6400|b) = half(1024+b), then -1024.
__device__ __forceinline__ uint2 byte2half2(unsigned w) {
    const __half2 off = __halves2half2(__ushort_as_half(0x6400), __ushort_as_half(0x6400));
    unsigned r0 = __byte_perm(w, 0, 0x4140) | 0x64006400u;   // {b0,b1} -> halves
    unsigned r1 = __byte_perm(w, 0, 0x4342) | 0x64006400u;   // {b2,b3}
    __half2 h0 = __hsub2(*reinterpret_cast<__half2*>(&r0), off);
    __half2 h1 = __hsub2(*reinterpret_cast<__half2*>(&r1), off);
    uint2 res;
    res.x = *reinterpret_cast<unsigned*>(&h0);
    res.y = *reinterpret_cast<unsigned*>(&h1);
    return res;
}

__global__ __launch_bounds__(256, 1)
void gemm_kernel(const float* __restrict__ scales, const int* __restrict__ qzeros,
                 const float* __restrict__ bias, const float* __restrict__ clampv,
                 float* __restrict__ out, int M, int N, int K) {
    extern __shared__ __half smem[];
    __half* As = smem;
    __half* Bs = smem + 2 * STAGE_A;

    const int tid = threadIdx.x;
    const int bm = blockIdx.y * BM;
    const int bn = blockIdx.x * BN;
    const __half* gA = g_qx + (size_t)bm * K;
    const unsigned char* gB = g_w8 + (size_t)bn * K;

    const int warp = tid >> 5, lane = tid & 31;
    const int wm = (warp >> 2) * 64;      // 2 warps along M
    const int wn = (warp & 3) * 64;       // 4 warps along N
    const int grp = lane >> 2, t4 = lane & 3;

    float acc[4][8][4];
    #pragma unroll
    for (int mi = 0; mi < 4; mi++)
        #pragma unroll
        for (int ni = 0; ni < 8; ni++)
            #pragma unroll
            for (int j = 0; j < 4; j++) acc[mi][ni][j] = 0.0f;

    const int KT = K / BK;
    uint4 bp[4];

    // ---- prologue: stage 0 ----
    #pragma unroll
    for (int i = 0; i < 4; i++) {
        int chunk = tid + i * 256;
        int m = chunk >> 3, kc = chunk & 7;
        cp_async16(As + m * PADK + kc * 8, gA + (size_t)m * K + kc * 8);
    }
    cp_async_commit();
    #pragma unroll
    for (int i = 0; i < 4; i++) {
        int chunk = tid + i * 256;
        int n = chunk >> 2, kc = chunk & 3;
        bp[i] = *reinterpret_cast<const uint4*>(gB + (size_t)n * K + kc * 16);
    }
    cp_async_wait0();
    #pragma unroll
    for (int i = 0; i < 4; i++) {
        int chunk = tid + i * 256;
        int n = chunk >> 2, kc = chunk & 3;
        __half* dst = Bs + n * PADK + kc * 16;
        uint2 p0 = byte2half2(bp[i].x), p1 = byte2half2(bp[i].y);
        uint2 p2 = byte2half2(bp[i].z), p3 = byte2half2(bp[i].w);
        uint4 lo; lo.x = p0.x; lo.y = p0.y; lo.z = p1.x; lo.w = p1.y;
        uint4 hi; hi.x = p2.x; hi.y = p2.y; hi.z = p3.x; hi.w = p3.y;
        *reinterpret_cast<uint4*>(dst)     = lo;
        *reinterpret_cast<uint4*>(dst + 8) = hi;
    }
    __syncthreads();

    // ---- main loop ----
    for (int kt = 0; kt < KT; kt++) {
        const int cur = kt & 1;
        const int nk0 = (kt + 1) * BK;
        if (kt + 1 < KT) {
            #pragma unroll
            for (int i = 0; i < 4; i++) {
                int chunk = tid + i * 256;
                int m = chunk >> 3, kc = chunk & 7;
                cp_async16(As + (cur ^ 1) * STAGE_A + m * PADK + kc * 8,
                           gA + (size_t)m * K + nk0 + kc * 8);
            }
            cp_async_commit();
            #pragma unroll
            for (int i = 0; i < 4; i++) {
                int chunk = tid + i * 256;
                int n = chunk >> 2, kc = chunk & 3;
                bp[i] = *reinterpret_cast<const uint4*>(gB + (size_t)n * K + nk0 + kc * 16);
            }
        }

        const __half* Ab = As + cur * STAGE_A;
        const __half* Bb = Bs + cur * STAGE_B;
        #pragma unroll
        for (int ks = 0; ks < 4; ks++) {
            const int k16 = ks * 16;
            unsigned a[4][4];
            #pragma unroll
            for (int mi = 0; mi < 4; mi++) {
                const __half* p = Ab + (wm + mi * 16 + grp) * PADK + k16 + t4 * 2;
                a[mi][0] = *reinterpret_cast<const unsigned*>(p);
                a[mi][1] = *reinterpret_cast<const unsigned*>(p + 8 * PADK);
                a[mi][2] = *reinterpret_cast<const unsigned*>(p + 8);
                a[mi][3] = *reinterpret_cast<const unsigned*>(p + 8 * PADK + 8);
            }
            #pragma unroll
            for (int ni = 0; ni < 8; ni++) {
                const __half* q = Bb + (wn + ni * 8 + grp) * PADK + k16 + t4 * 2;
                unsigned b0 = *reinterpret_cast<const unsigned*>(q);
                unsigned b1 = *reinterpret_cast<const unsigned*>(q + 8);
                #pragma unroll
                for (int mi = 0; mi < 4; mi++)
                    mma16816(acc[mi][ni], a[mi], b0, b1);
            }
        }

        if (kt + 1 < KT) {
            #pragma unroll
            for (int i = 0; i < 4; i++) {
                int chunk = tid + i * 256;
                int n = chunk >> 2, kc = chunk & 3;
                __half* dst = Bs + (cur ^ 1) * STAGE_B + n * PADK + kc * 16;
                uint2 p0 = byte2half2(bp[i].x), p1 = byte2half2(bp[i].y);
                uint2 p2 = byte2half2(bp[i].z), p3 = byte2half2(bp[i].w);
                uint4 lo; lo.x = p0.x; lo.y = p0.y; lo.z = p1.x; lo.w = p1.y;
                uint4 hi; hi.x = p2.x; hi.y = p2.y; hi.z = p3.x; hi.w = p3.y;
                *reinterpret_cast<uint4*>(dst)     = lo;
                *reinterpret_cast<uint4*>(dst + 8) = hi;
            }
            cp_async_wait0();
        }
        __syncthreads();
    }

    // ---- epilogue: out = a_scale*scale[n]*(acc - z[n]*rowsum[m]) + bias[n] ----
    const float cv = __ldg(clampv);
    const float a_scale = cv / 127.0f;
    float rs[4][2];
    #pragma unroll
    for (int mi = 0; mi < 4; mi++) {
        rs[mi][0] = g_rowsum[bm + wm + mi * 16 + grp];
        rs[mi][1] = g_rowsum[bm + wm + mi * 16 + grp + 8];
    }
    #pragma unroll
    for (int ni = 0; ni < 8; ni++) {
        const int c = bn + wn + ni * 8 + t4 * 2;
        const float s0 = a_scale * __ldg(scales + c);
        const float s1 = a_scale * __ldg(scales + c + 1);
        const float z0 = s0 * (float)__ldg(qzeros + c);
        const float z1 = s1 * (float)__ldg(qzeros + c + 1);
        const float b0 = __ldg(bias + c);
        const float b1 = __ldg(bias + c + 1);
        #pragma unroll
        for (int mi = 0; mi < 4; mi++) {
            const int r0 = bm + wm + mi * 16 + grp;
            float2 o0, o1;
            o0.x = s0 * acc[mi][ni][0] - z0 * rs[mi][0] + b0;
            o0.y = s1 * acc[mi][ni][1] - z1 * rs[mi][0] + b1;
            o1.x = s0 * acc[mi][ni][2] - z0 * rs[mi][1] + b0;
            o1.y = s1 * acc[mi][ni][3] - z1 * rs[mi][1] + b1;
            *reinterpret_cast<float2*>(out + (size_t)r0 * N + c)       = o0;
            *reinterpret_cast<float2*>(out + (size_t)(r0 + 8) * N + c) = o1;
        }
    }
}

// ---------------------------------------------------------------------------
extern "C" void kernel_launch(void* const* d_in, const int* in_sizes, int n_in,
                              void* d_out, int out_size) {
    const float* x      = (const float*)d_in[0];
    const int*   qw     = (const int*)  d_in[1];
    const int*   qz     = (const int*)  d_in[2];
    const float* scales = (const float*)d_in[3];
    const float* bias   = (const float*)d_in[4];
    const float* clampv = (const float*)d_in[5];

    const int OUT = in_sizes[2];                         // 11008 (qzeros count)
    const int IN  = (int)((2ll * in_sizes[1]) / OUT);    // 4096
    const int M   = (int)((long long)in_sizes[0] / IN);  // 4096

    quantize_kernel<<<M, 256>>>(x, clampv, IN);

    long long ngroups = (long long)OUT * IN / 8;
    unpack_kernel<<<(unsigned)((ngroups + 255) / 256), 256>>>(qw, ngroups);

    cudaFuncSetAttribute(gemm_kernel,
                         cudaFuncAttributeMaxDynamicSharedMemorySize, SMEM_BYTES);
    dim3 grid(OUT / BN, M / BM);   // 43 x 32
    gemm_kernel<<<grid, 256, SMEM_BYTES>>>(scales, qz, bias, clampv,
                                           (float*)d_out, M, OUT, IN);
}